// round 9
// baseline (speedup 1.0000x reference)
#include <cuda_runtime.h>
#include <cuda_fp16.h>
#include <cstdint>

#define Nn 100000
#define Mm 800000
#define CAP 48

// ---------------- device scratch (no allocations allowed) ----------------
__device__ __half  g_xh[(size_t)Nn * 64];      // fp16 copy of x
__device__ __half  g_aggXh[(size_t)Nn * 128];  // per-node [type0(64)|type1(64)] src-sums
__device__ float   g_aggE[(size_t)Nn * 48];    // aggregated edge_feat [N][3][16] fp32
__device__ int     g_cur[Nn];                  // packed: tot(10)|c1(10)|c2(10)
__device__ int     g_slots[(size_t)Nn * CAP];  // bucket payload: src per edge
__device__ uint32_t g_nh[Nn];                  // half2(n0, n1) bucketed src-type counts
__device__ int     g_ovf_cnt;
__device__ int2    g_ovf[8192];                // overflow edges (src, dst)

__device__ __forceinline__ void red_add_f4(float4* p, float4 v) {
    asm volatile("red.global.add.v4.f32 [%0], {%1,%2,%3,%4};"
                 :: "l"(p), "f"(v.x), "f"(v.y), "f"(v.z), "f"(v.w)
                 : "memory");
}

__device__ __forceinline__ void mma_f16(float c[4], uint32_t a0, uint32_t a1,
                                        uint32_t a2, uint32_t a3,
                                        uint32_t b0, uint32_t b1) {
    asm volatile(
        "mma.sync.aligned.m16n8k16.row.col.f32.f16.f16.f32 "
        "{%0,%1,%2,%3},{%4,%5,%6,%7},{%8,%9},{%0,%1,%2,%3};"
        : "+f"(c[0]), "+f"(c[1]), "+f"(c[2]), "+f"(c[3])
        : "r"(a0), "r"(a1), "r"(a2), "r"(a3), "r"(b0), "r"(b1));
}

__device__ __forceinline__ uint32_t pack_h2(float a, float b) {
    __half2 h = __floats2half2_rn(a, b);
    return *(uint32_t*)&h;
}

// ---------------- kernels ----------------

// zero aggE + cursors, and convert x -> fp16
__global__ void zero_conv_kernel(const float* __restrict__ x) {
    int gid = blockIdx.x * blockDim.x + threadIdx.x;
    int stride = gridDim.x * blockDim.x;
    uint32_t* xh32 = (uint32_t*)g_xh;
    const float2* x2 = (const float2*)x;
    for (int i = gid; i < Nn * 32; i += stride) {
        float2 v = x2[i];
        xh32[i] = pack_h2(v.x, v.y);
    }
    float4* e4 = (float4*)g_aggE;
    float4 z = make_float4(0.f, 0.f, 0.f, 0.f);
    for (int i = gid; i < Nn * 12; i += stride) e4[i] = z;
    for (int i = gid; i < Nn; i += stride) g_cur[i] = 0;
    if (gid == 0) g_ovf_cnt = 0;
}

// 4 threads/edge: red.v4 aggE[dst][etype] + packed count atomic + bucket fill
__global__ void edge_scatter_kernel(const float* __restrict__ ef,
                                    const int* __restrict__ esrc,
                                    const int* __restrict__ edst,
                                    const int* __restrict__ etype) {
    int gid = blockIdx.x * blockDim.x + threadIdx.x;
    int e = gid >> 2, q = gid & 3;
    if (e >= Mm) return;
    int dst = edst[e];
    int t   = etype[e];
    float4 v = ((const float4*)ef)[e * 4 + q];
    red_add_f4(&((float4*)g_aggE)[dst * 12 + t * 4 + q], v);
    if (q == 0) {
        int inc = 1 + ((t == 1) ? (1 << 10) : 0) + ((t == 2) ? (1 << 20) : 0);
        int old = atomicAdd(&g_cur[dst], inc);
        int p = old & 1023;
        int src = esrc[e];
        if (p < CAP) {
            g_slots[(size_t)dst * CAP + p] = src;
        } else {
            int o = atomicAdd(&g_ovf_cnt, 1);
            if (o < 8192) g_ovf[o] = make_int2(src, dst);
        }
    }
}

// Bucket gather of x (fp16) into per-(dst, src-type) sums. 16 lanes/node.
__global__ __launch_bounds__(256)
void gatherx_kernel(const int* __restrict__ ntype) {
    int tid = threadIdx.x;
    int node = blockIdx.x * 16 + (tid >> 4);
    int q = tid & 15;
    if (node >= Nn) return;
    int tot = g_cur[node] & 1023;
    int deg = (tot > CAP) ? CAP : tot;

    const uint2* X = (const uint2*)g_xh;
    const int* sl = &g_slots[(size_t)node * CAP];
    float4 a0 = make_float4(0.f, 0.f, 0.f, 0.f);
    float4 a1 = make_float4(0.f, 0.f, 0.f, 0.f);
    int n1 = 0;

    auto addsel = [&](int t, uint2 hv) {
        float2 f0 = __half22float2(*(__half2*)&hv.x);
        float2 f1 = __half22float2(*(__half2*)&hv.y);
        float m1 = (float)t, m0 = 1.f - m1;
        a0.x += m0 * f0.x; a0.y += m0 * f0.y; a0.z += m0 * f1.x; a0.w += m0 * f1.y;
        a1.x += m1 * f0.x; a1.y += m1 * f0.y; a1.z += m1 * f1.x; a1.w += m1 * f1.y;
        n1 += t;
    };

    int i = 0;
    for (; i + 4 <= deg; i += 4) {
        int s[4];
        #pragma unroll
        for (int u = 0; u < 4; u++) s[u] = __ldg(&sl[i + u]);
        int t[4]; uint2 v[4];
        #pragma unroll
        for (int u = 0; u < 4; u++) { t[u] = __ldg(&ntype[s[u]]); v[u] = __ldg(&X[s[u] * 16 + q]); }
        #pragma unroll
        for (int u = 0; u < 4; u++) addsel(t[u], v[u]);
    }
    for (; i < deg; i++) {
        int s = __ldg(&sl[i]);
        addsel(__ldg(&ntype[s]), __ldg(&X[s * 16 + q]));
    }

    uint2* A = (uint2*)g_aggXh;
    A[node * 32 + q]      = make_uint2(pack_h2(a0.x, a0.y), pack_h2(a0.z, a0.w));
    A[node * 32 + 16 + q] = make_uint2(pack_h2(a1.x, a1.y), pack_h2(a1.z, a1.w));
    if (q == 0) g_nh[node] = pack_h2((float)(deg - n1), (float)n1);
}

// Mega GEMM (fp16 m16n8k16), warp-autonomous, single 64-col output, k=320:
// A row = [x(t=0 slot:64) | x(t=1:64) | aggX0(64) | aggX1(64) | aggE(48) |
//          c0,c1,c2,n0,n1 | 0...]  (type selection on A side; B type-free)
// B rows: 0..63 W1[0], 64..127 W1[1], 128..191 W2[0], 192..255 W2[1],
//         256..303 W5, 304..306 b5, 307 b2[0], 308 b2[1], rest 0.
// Epilogue: out[node] = acc + b1[t].  Written exactly once.
__global__ __launch_bounds__(256, 2)
void mega_gemm_kernel(const int* __restrict__ ntype,
                      const float* __restrict__ W1, const float* __restrict__ b1,
                      const float* __restrict__ W2, const float* __restrict__ b2,
                      const float* __restrict__ W5, const float* __restrict__ b5,
                      float* __restrict__ out) {
    extern __shared__ uint32_t smu[];
    uint4* Wf = (uint4*)smu;                 // [20][4][32] uint4 = 40 KB
    float* bc = (float*)(smu + 10240);       // [128] b1 (both types)

    const int tid = threadIdx.x;
    const int w = tid >> 5, lane = tid & 31;
    const int g = lane >> 2, tq = lane & 3;

    // ---- one-time B fill, fragment order ----
    {
        auto w_src = [&](int kk, int c) -> float {
            if (kk < 64)  return W1[kk * 64 + c];
            if (kk < 128) return W1[4096 + (kk - 64) * 64 + c];
            if (kk < 192) return W2[(kk - 128) * 64 + c];
            if (kk < 256) return W2[4096 + (kk - 192) * 64 + c];
            if (kk < 304) return W5[(kk - 256) * 64 + c];
            if (kk < 307) return b5[(kk - 304) * 64 + c];
            if (kk == 307) return b2[c];
            if (kk == 308) return b2[64 + c];
            return 0.f;
        };
        for (int idx = tid; idx < 2560; idx += 256) {
            int ln = idx & 31;
            int ntp = (idx >> 5) & 3;
            int kb = idx >> 7;                // 0..19
            int tqf = ln & 3, gf = ln >> 2;
            int ka = 16 * kb + 2 * tqf;       // halves (ka, ka+1)
            int kbh = ka + 8;
            int col0 = (2 * ntp) * 8 + gf;
            int col1 = col0 + 8;
            uint4 wv;
            wv.x = pack_h2(w_src(ka, col0), w_src(ka + 1, col0));
            wv.y = pack_h2(w_src(kbh, col0), w_src(kbh + 1, col0));
            wv.z = pack_h2(w_src(ka, col1), w_src(ka + 1, col1));
            wv.w = pack_h2(w_src(kbh, col1), w_src(kbh + 1, col1));
            Wf[idx] = wv;
        }
        if (tid < 128) bc[tid] = b1[tid];
    }
    __syncthreads();   // only barrier

    const int G = Nn >> 4;                   // 6250 groups of 16
    const int nwarps = gridDim.x << 3;
    float2* outp = (float2*)out;
    const uint32_t* xh32 = (const uint32_t*)g_xh;
    const uint32_t* ax32 = (const uint32_t*)g_aggXh;

    for (int grp = blockIdx.x * 8 + w; grp < G; grp += nwarps) {
        int base = grp << 4;
        int nd[2], tt[2];
        uint32_t xw[2][8], axw[2][16], tw[2][8];

        #pragma unroll
        for (int j = 0; j < 2; j++) {
            int node = base + g + 8 * j;
            nd[j] = node;
            tt[j] = __ldg(&ntype[node]);
            const uint32_t* xp = xh32 + (size_t)node * 32;
            #pragma unroll
            for (int m = 0; m < 4; m++) {
                xw[j][2 * m]     = xp[8 * m + tq];
                xw[j][2 * m + 1] = xp[8 * m + 4 + tq];
            }
            const uint32_t* ap = ax32 + (size_t)node * 64;
            #pragma unroll
            for (int m = 0; m < 8; m++) {
                axw[j][2 * m]     = ap[8 * m + tq];
                axw[j][2 * m + 1] = ap[8 * m + 4 + tq];
            }
            // tail: aggE words + counts
            int cv = __ldg(&g_cur[node]);
            int tot = cv & 1023, c1i = (cv >> 10) & 1023, c2i = cv >> 20;
            float c0f = (float)(tot - c1i - c2i);
            uint32_t nh = g_nh[node];
            __half2 nh2 = *(__half2*)&nh;
            float n0f = __low2float(nh2), n1f = __high2float(nh2);
            const float* ep = g_aggE + (size_t)node * 48;
            auto tail_word = [&](int wd) -> uint32_t {
                if (wd < 24) { float2 v = *(const float2*)(ep + 2 * wd); return pack_h2(v.x, v.y); }
                if (wd == 24) return pack_h2(c0f, (float)c1i);
                if (wd == 25) return pack_h2((float)c2i, n0f);
                if (wd == 26) return pack_h2(n1f, 0.f);
                return 0u;
            };
            #pragma unroll
            for (int m = 0; m < 4; m++) {
                tw[j][2 * m]     = tail_word(8 * m + tq);
                tw[j][2 * m + 1] = tail_word(8 * m + 4 + tq);
            }
        }

        float acc[8][4];
        #pragma unroll
        for (int nt = 0; nt < 8; nt++)
            #pragma unroll
            for (int jj = 0; jj < 4; jj++) acc[nt][jj] = 0.f;

        #pragma unroll
        for (int kb = 0; kb < 20; kb++) {
            uint32_t a0, a1, a2, a3;
            if (kb < 4) {
                a0 = (tt[0] == 0) ? xw[0][2 * kb] : 0u;
                a2 = (tt[0] == 0) ? xw[0][2 * kb + 1] : 0u;
                a1 = (tt[1] == 0) ? xw[1][2 * kb] : 0u;
                a3 = (tt[1] == 0) ? xw[1][2 * kb + 1] : 0u;
            } else if (kb < 8) {
                int m = kb - 4;
                a0 = (tt[0] == 1) ? xw[0][2 * m] : 0u;
                a2 = (tt[0] == 1) ? xw[0][2 * m + 1] : 0u;
                a1 = (tt[1] == 1) ? xw[1][2 * m] : 0u;
                a3 = (tt[1] == 1) ? xw[1][2 * m + 1] : 0u;
            } else if (kb < 16) {
                int m = kb - 8;
                a0 = axw[0][2 * m]; a2 = axw[0][2 * m + 1];
                a1 = axw[1][2 * m]; a3 = axw[1][2 * m + 1];
            } else {
                int m = kb - 16;
                a0 = tw[0][2 * m]; a2 = tw[0][2 * m + 1];
                a1 = tw[1][2 * m]; a3 = tw[1][2 * m + 1];
            }
            #pragma unroll
            for (int ntp = 0; ntp < 4; ntp++) {
                uint4 bw = Wf[(kb * 4 + ntp) * 32 + lane];
                mma_f16(acc[2 * ntp], a0, a1, a2, a3, bw.x, bw.y);
                mma_f16(acc[2 * ntp + 1], a0, a1, a2, a3, bw.z, bw.w);
            }
        }

        #pragma unroll
        for (int j = 0; j < 2; j++) {
            int t = tt[j];
            int node = nd[j];
            #pragma unroll
            for (int nt = 0; nt < 8; nt++) {
                int col0 = nt * 8 + 2 * tq;
                float v0 = acc[nt][2 * j + 0] + bc[t * 64 + col0];
                float v1 = acc[nt][2 * j + 1] + bc[t * 64 + col0 + 1];
                outp[(size_t)node * 32 + nt * 4 + tq] = make_float2(v0, v1);
            }
        }
    }
}

// Rare overflow edges (deg > CAP): add W2[t]*x[src] + b2[t] to out[dst].
// One warp per edge, fp32.
__global__ void ovf_kernel(const float* __restrict__ x,
                           const int* __restrict__ ntype,
                           const float* __restrict__ W2,
                           const float* __restrict__ b2,
                           float* __restrict__ out) {
    int n = g_ovf_cnt;
    if (n > 8192) n = 8192;
    int wid = (blockIdx.x * blockDim.x + threadIdx.x) >> 5;
    int lane = threadIdx.x & 31;
    int nwarps = (gridDim.x * blockDim.x) >> 5;
    for (int ei = wid; ei < n; ei += nwarps) {
        int2 sd = g_ovf[ei];
        int src = sd.x, dst = sd.y;
        int t = ntype[src];
        int c = lane * 2;
        float s0 = b2[t * 64 + c], s1 = b2[t * 64 + c + 1];
        for (int k = 0; k < 64; k++) {
            float xv = __ldg(&x[src * 64 + k]);
            s0 += xv * __ldg(&W2[t * 4096 + k * 64 + c]);
            s1 += xv * __ldg(&W2[t * 4096 + k * 64 + c + 1]);
        }
        atomicAdd(&out[(size_t)dst * 64 + c], s0);
        atomicAdd(&out[(size_t)dst * 64 + c + 1], s1);
    }
}

// ---------------- launch ----------------
extern "C" void kernel_launch(void* const* d_in, const int* in_sizes, int n_in,
                              void* d_out, int out_size) {
    const float *x = nullptr, *ef = nullptr;
    const float *W[4] = {nullptr, nullptr, nullptr, nullptr};
    const float *B[4] = {nullptr, nullptr, nullptr, nullptr};
    const float *W5 = nullptr, *b5 = nullptr;
    const int *ntype = nullptr, *esrc = nullptr, *edst = nullptr, *etype = nullptr;
    int wI = 0, bI = 0, mI = 0;
    for (int i = 0; i < n_in; i++) {
        long s = in_sizes[i];
        const void* p = d_in[i];
        if (s == (long)Nn * 64)       x = (const float*)p;
        else if (s == (long)Mm * 16)  ef = (const float*)p;
        else if (s == Nn)             ntype = (const int*)p;
        else if (s == Mm) {
            if (mI == 0) esrc = (const int*)p;
            else if (mI == 1) edst = (const int*)p;
            else etype = (const int*)p;
            mI++;
        }
        else if (s == 2 * 64 * 64) { if (wI < 4) W[wI++] = (const float*)p; }
        else if (s == 2 * 64)      { if (bI < 4) B[bI++] = (const float*)p; }
        else if (s == 3 * 16 * 64) W5 = (const float*)p;
        else if (s == 3 * 64)      b5 = (const float*)p;
    }
    float* out = (float*)d_out;

    const int smem_bytes = 2560 * 16 + 128 * 4;   // 41472
    cudaFuncSetAttribute(mega_gemm_kernel,
                         cudaFuncAttributeMaxDynamicSharedMemorySize, 48 * 1024);

    zero_conv_kernel<<<2048, 256>>>(x);
    edge_scatter_kernel<<<(Mm * 4 + 255) / 256, 256>>>(ef, esrc, edst, etype);
    gatherx_kernel<<<(Nn + 15) / 16, 256>>>(ntype);
    mega_gemm_kernel<<<296, 256, smem_bytes>>>(
        ntype, W[0], B[0], W[1], B[1], W5, b5, out);
    ovf_kernel<<<8, 256>>>(x, ntype, W[1], B[1], out);
}

// round 10
// speedup vs baseline: 1.2751x; 1.2751x over previous
#include <cuda_runtime.h>
#include <cuda_fp16.h>
#include <cstdint>

#define Nn 100000
#define Mm 800000
#define CAP 48

// ---------------- device scratch (no allocations allowed) ----------------
__device__ __half  g_h2h[(size_t)Nn * 64];    // h2 rows fp16 (128B/row)
__device__ uint4   g_aggEh4[(size_t)Nn * 6];  // aggE fp16 [N][3][16] halves
__device__ int     g_cur[Nn];                 // packed: tot(10)|c1(10)|c2(10)
__device__ int     g_slots[(size_t)Nn * CAP]; // bucket payload: src per edge
__device__ int     g_ovf_cnt;
__device__ int2    g_ovf[8192];               // overflow edges (src, dst)

__device__ __forceinline__ void red_add_h8(uint32_t* p, uint32_t a, uint32_t b,
                                           uint32_t c, uint32_t d) {
    asm volatile("red.global.add.noftz.v4.f16x2 [%0], {%1,%2,%3,%4};"
                 :: "l"(p), "r"(a), "r"(b), "r"(c), "r"(d) : "memory");
}

__device__ __forceinline__ void mma_f16(float c[4], uint32_t a0, uint32_t a1,
                                        uint32_t a2, uint32_t a3,
                                        uint32_t b0, uint32_t b1) {
    asm volatile(
        "mma.sync.aligned.m16n8k16.row.col.f32.f16.f16.f32 "
        "{%0,%1,%2,%3},{%4,%5,%6,%7},{%8,%9},{%0,%1,%2,%3};"
        : "+f"(c[0]), "+f"(c[1]), "+f"(c[2]), "+f"(c[3])
        : "r"(a0), "r"(a1), "r"(a2), "r"(a3), "r"(b0), "r"(b1));
}

__device__ __forceinline__ uint32_t pack_h2(float a, float b) {
    __half2 h = __floats2half2_rn(a, b);
    return *(uint32_t*)&h;
}

// ---------------- kernels ----------------

__global__ void zero_kernel() {
    int gid = blockIdx.x * blockDim.x + threadIdx.x;
    int stride = gridDim.x * blockDim.x;
    uint4 z = make_uint4(0u, 0u, 0u, 0u);
    for (int i = gid; i < Nn * 6; i += stride) g_aggEh4[i] = z;
    for (int i = gid; i < Nn; i += stride) g_cur[i] = 0;
    if (gid == 0) g_ovf_cnt = 0;
}

// 2 threads/edge: fp16x8 red into aggEh[dst][etype] + packed cursor + bucket
__global__ void edge_scatter_kernel(const float* __restrict__ ef,
                                    const int* __restrict__ esrc,
                                    const int* __restrict__ edst,
                                    const int* __restrict__ etype) {
    int gid = blockIdx.x * blockDim.x + threadIdx.x;
    int e = gid >> 1, q = gid & 1;
    if (e >= Mm) return;
    int dst = edst[e];
    int t   = etype[e];
    const float4* ef4 = (const float4*)ef;
    float4 v0 = ef4[e * 4 + q * 2];
    float4 v1 = ef4[e * 4 + q * 2 + 1];
    uint32_t h0 = pack_h2(v0.x, v0.y), h1 = pack_h2(v0.z, v0.w);
    uint32_t h2 = pack_h2(v1.x, v1.y), h3 = pack_h2(v1.z, v1.w);
    uint32_t* base = (uint32_t*)g_aggEh4;
    red_add_h8(base + (size_t)dst * 24 + t * 8 + q * 4, h0, h1, h2, h3);
    if (q == 0) {
        int inc = 1 + ((t == 1) ? (1 << 10) : 0) + ((t == 2) ? (1 << 20) : 0);
        int old = atomicAdd(&g_cur[dst], inc);
        int p = old & 1023;
        int src = esrc[e];
        if (p < CAP) {
            g_slots[(size_t)dst * CAP + p] = src;
        } else {
            int o = atomicAdd(&g_ovf_cnt, 1);
            if (o < 8192) g_ovf[o] = make_int2(src, dst);
        }
    }
}

// h2 GEMM (independent of edges; runs on side stream).
// A row = [x * (t==0) (64) | x * (t==1) (64)], k=128. B = [W2[0]; W2[1]].
// h2h[node] = fp16(acc + b2[t]).  Warp-autonomous, 16 nodes/warp-group.
__global__ __launch_bounds__(256, 2)
void h2_gemm_kernel(const float* __restrict__ x,
                    const int* __restrict__ ntype,
                    const float* __restrict__ W2, const float* __restrict__ b2) {
    extern __shared__ uint32_t smu[];
    uint4* Wf = (uint4*)smu;                 // [8][4][32] uint4 = 16 KB
    float* bc = (float*)(smu + 4096);        // [128] b2 both types

    const int tid = threadIdx.x;
    const int w = tid >> 5, lane = tid & 31;
    const int g = lane >> 2, tq = lane & 3;

    for (int idx = tid; idx < 1024; idx += 256) {
        int ln = idx & 31;
        int ntp = (idx >> 5) & 3;
        int kb = idx >> 7;                    // 0..7
        int tqf = ln & 3, gf = ln >> 2;
        int ka = 16 * kb + 2 * tqf;           // half index (ka, ka+1)
        int kbh = ka + 8;
        int col0 = (2 * ntp) * 8 + gf;
        int col1 = col0 + 8;
        auto w_src = [&](int kk, int c) -> float {
            return (kk < 64) ? W2[kk * 64 + c] : W2[4096 + (kk - 64) * 64 + c];
        };
        uint4 wv;
        wv.x = pack_h2(w_src(ka, col0), w_src(ka + 1, col0));
        wv.y = pack_h2(w_src(kbh, col0), w_src(kbh + 1, col0));
        wv.z = pack_h2(w_src(ka, col1), w_src(ka + 1, col1));
        wv.w = pack_h2(w_src(kbh, col1), w_src(kbh + 1, col1));
        Wf[idx] = wv;
    }
    if (tid < 128) bc[tid] = b2[tid];
    __syncthreads();

    const int G = Nn >> 4;
    const int nwarps = gridDim.x << 3;
    __half2* h2p = (__half2*)g_h2h;

    for (int grp = blockIdx.x * 8 + w; grp < G; grp += nwarps) {
        int base = grp << 4;
        uint32_t xw[2][8], msk[2];
        int tt[2];
        #pragma unroll
        for (int j = 0; j < 2; j++) {
            int node = base + g + 8 * j;
            tt[j] = __ldg(&ntype[node]);
            msk[j] = (tt[j] == 0) ? 0xFFFFFFFFu : 0u;
            const float2* xp = (const float2*)(x + (size_t)node * 64);
            #pragma unroll
            for (int m = 0; m < 4; m++) {
                float2 va = xp[8 * m + tq];
                float2 vb = xp[8 * m + 4 + tq];
                xw[j][2 * m]     = pack_h2(va.x, va.y);
                xw[j][2 * m + 1] = pack_h2(vb.x, vb.y);
            }
        }

        float acc[8][4];
        #pragma unroll
        for (int nt = 0; nt < 8; nt++)
            #pragma unroll
            for (int jj = 0; jj < 4; jj++) acc[nt][jj] = 0.f;

        #pragma unroll
        for (int kb = 0; kb < 8; kb++) {
            int m = kb & 3;
            uint32_t s0 = (kb < 4) ? msk[0] : ~msk[0];
            uint32_t s1 = (kb < 4) ? msk[1] : ~msk[1];
            uint32_t a0 = xw[0][2 * m] & s0;
            uint32_t a2 = xw[0][2 * m + 1] & s0;
            uint32_t a1 = xw[1][2 * m] & s1;
            uint32_t a3 = xw[1][2 * m + 1] & s1;
            #pragma unroll
            for (int ntp = 0; ntp < 4; ntp++) {
                uint4 bw = Wf[(kb * 4 + ntp) * 32 + lane];
                mma_f16(acc[2 * ntp], a0, a1, a2, a3, bw.x, bw.y);
                mma_f16(acc[2 * ntp + 1], a0, a1, a2, a3, bw.z, bw.w);
            }
        }

        #pragma unroll
        for (int j = 0; j < 2; j++) {
            int node = base + g + 8 * j;
            int t = tt[j];
            #pragma unroll
            for (int nt = 0; nt < 8; nt++) {
                int col0 = nt * 8 + 2 * tq;
                float v0 = acc[nt][2 * j + 0] + bc[t * 64 + col0];
                float v1 = acc[nt][2 * j + 1] + bc[t * 64 + col0 + 1];
                h2p[(size_t)node * 32 + nt * 4 + tq] = __floats2half2_rn(v0, v1);
            }
        }
    }
}

// h1 GEMM: A row = [x*(t==0)(64) | x*(t==1)(64) | aggE(48) | c0,c1,c2 | 0(13)]
// k=192. B = [W1[0]; W1[1]; W5; b5; 0]. out[node] = acc + b1[t], written once.
__global__ __launch_bounds__(256, 2)
void h1_gemm_kernel(const float* __restrict__ x,
                    const int* __restrict__ ntype,
                    const float* __restrict__ W1, const float* __restrict__ b1,
                    const float* __restrict__ W5, const float* __restrict__ b5,
                    float* __restrict__ out) {
    extern __shared__ uint32_t smu[];
    uint4* Wf = (uint4*)smu;                 // [12][4][32] uint4 = 24 KB
    float* bc = (float*)(smu + 6144);        // [128] b1 both types

    const int tid = threadIdx.x;
    const int w = tid >> 5, lane = tid & 31;
    const int g = lane >> 2, tq = lane & 3;

    for (int idx = tid; idx < 1536; idx += 256) {
        int ln = idx & 31;
        int ntp = (idx >> 5) & 3;
        int kb = idx >> 7;                    // 0..11
        int tqf = ln & 3, gf = ln >> 2;
        int ka = 16 * kb + 2 * tqf;
        int kbh = ka + 8;
        int col0 = (2 * ntp) * 8 + gf;
        int col1 = col0 + 8;
        auto w_src = [&](int kk, int c) -> float {
            if (kk < 64)  return W1[kk * 64 + c];
            if (kk < 128) return W1[4096 + (kk - 64) * 64 + c];
            if (kk < 176) return W5[(kk - 128) * 64 + c];
            if (kk < 179) return b5[(kk - 176) * 64 + c];
            return 0.f;
        };
        uint4 wv;
        wv.x = pack_h2(w_src(ka, col0), w_src(ka + 1, col0));
        wv.y = pack_h2(w_src(kbh, col0), w_src(kbh + 1, col0));
        wv.z = pack_h2(w_src(ka, col1), w_src(ka + 1, col1));
        wv.w = pack_h2(w_src(kbh, col1), w_src(kbh + 1, col1));
        Wf[idx] = wv;
    }
    if (tid < 128) bc[tid] = b1[tid];
    __syncthreads();

    const int G = Nn >> 4;
    const int nwarps = gridDim.x << 3;
    float2* outp = (float2*)out;
    const uint32_t* agg32 = (const uint32_t*)g_aggEh4;

    for (int grp = blockIdx.x * 8 + w; grp < G; grp += nwarps) {
        int base = grp << 4;
        uint32_t xw[2][8], tw[2][8], msk[2];
        int tt[2];
        #pragma unroll
        for (int j = 0; j < 2; j++) {
            int node = base + g + 8 * j;
            tt[j] = __ldg(&ntype[node]);
            msk[j] = (tt[j] == 0) ? 0xFFFFFFFFu : 0u;
            const float2* xp = (const float2*)(x + (size_t)node * 64);
            #pragma unroll
            for (int m = 0; m < 4; m++) {
                float2 va = xp[8 * m + tq];
                float2 vb = xp[8 * m + 4 + tq];
                xw[j][2 * m]     = pack_h2(va.x, va.y);
                xw[j][2 * m + 1] = pack_h2(vb.x, vb.y);
            }
            int cv = __ldg(&g_cur[node]);
            int tot = cv & 1023, c1i = (cv >> 10) & 1023, c2i = cv >> 20;
            float c0f = (float)(tot - c1i - c2i);
            const uint32_t* ap = agg32 + (size_t)node * 24;
            auto tail_word = [&](int rel) -> uint32_t {
                if (rel < 24) return __ldg(&ap[rel]);
                if (rel == 24) return pack_h2(c0f, (float)c1i);
                if (rel == 25) return pack_h2((float)c2i, 0.f);
                return 0u;
            };
            #pragma unroll
            for (int m = 0; m < 4; m++) {
                tw[j][2 * m]     = tail_word(8 * m + tq);
                tw[j][2 * m + 1] = tail_word(8 * m + 4 + tq);
            }
        }

        float acc[8][4];
        #pragma unroll
        for (int nt = 0; nt < 8; nt++)
            #pragma unroll
            for (int jj = 0; jj < 4; jj++) acc[nt][jj] = 0.f;

        #pragma unroll
        for (int kb = 0; kb < 12; kb++) {
            uint32_t a0, a1, a2, a3;
            if (kb < 8) {
                int m = kb & 3;
                uint32_t s0 = (kb < 4) ? msk[0] : ~msk[0];
                uint32_t s1 = (kb < 4) ? msk[1] : ~msk[1];
                a0 = xw[0][2 * m] & s0;
                a2 = xw[0][2 * m + 1] & s0;
                a1 = xw[1][2 * m] & s1;
                a3 = xw[1][2 * m + 1] & s1;
            } else {
                int m = kb - 8;
                a0 = tw[0][2 * m]; a2 = tw[0][2 * m + 1];
                a1 = tw[1][2 * m]; a3 = tw[1][2 * m + 1];
            }
            #pragma unroll
            for (int ntp = 0; ntp < 4; ntp++) {
                uint4 bw = Wf[(kb * 4 + ntp) * 32 + lane];
                mma_f16(acc[2 * ntp], a0, a1, a2, a3, bw.x, bw.y);
                mma_f16(acc[2 * ntp + 1], a0, a1, a2, a3, bw.z, bw.w);
            }
        }

        #pragma unroll
        for (int j = 0; j < 2; j++) {
            int node = base + g + 8 * j;
            int t = tt[j];
            #pragma unroll
            for (int nt = 0; nt < 8; nt++) {
                int col0 = nt * 8 + 2 * tq;
                float v0 = acc[nt][2 * j + 0] + bc[t * 64 + col0];
                float v1 = acc[nt][2 * j + 1] + bc[t * 64 + col0 + 1];
                outp[(size_t)node * 32 + nt * 4 + tq] = make_float2(v0, v1);
            }
        }
    }
}

// Bucket gather: out[dst] += sum h2[src]; 8 lanes/node, uint4 loads.
__global__ __launch_bounds__(256)
void h2_gather_kernel(float* __restrict__ out) {
    int tid = threadIdx.x;
    int node = blockIdx.x * 32 + (tid >> 3);
    int q = tid & 7;
    if (node >= Nn) return;
    int deg = g_cur[node] & 1023;
    if (deg > CAP) deg = CAP;
    if (deg == 0) return;

    const uint4* H = (const uint4*)g_h2h;
    const int* sl = &g_slots[(size_t)node * CAP];
    float acc[8];
    #pragma unroll
    for (int u = 0; u < 8; u++) acc[u] = 0.f;

    auto add8 = [&](uint4 hv) {
        float2 f0 = __half22float2(*(__half2*)&hv.x);
        float2 f1 = __half22float2(*(__half2*)&hv.y);
        float2 f2 = __half22float2(*(__half2*)&hv.z);
        float2 f3 = __half22float2(*(__half2*)&hv.w);
        acc[0] += f0.x; acc[1] += f0.y; acc[2] += f1.x; acc[3] += f1.y;
        acc[4] += f2.x; acc[5] += f2.y; acc[6] += f3.x; acc[7] += f3.y;
    };

    int i = 0;
    for (; i + 8 <= deg; i += 8) {
        int s[8];
        #pragma unroll
        for (int u = 0; u < 8; u++) s[u] = __ldg(&sl[i + u]);
        uint4 v[8];
        #pragma unroll
        for (int u = 0; u < 8; u++) v[u] = __ldg(&H[(size_t)s[u] * 8 + q]);
        #pragma unroll
        for (int u = 0; u < 8; u++) add8(v[u]);
    }
    for (; i + 4 <= deg; i += 4) {
        int s[4];
        #pragma unroll
        for (int u = 0; u < 4; u++) s[u] = __ldg(&sl[i + u]);
        uint4 v[4];
        #pragma unroll
        for (int u = 0; u < 4; u++) v[u] = __ldg(&H[(size_t)s[u] * 8 + q]);
        #pragma unroll
        for (int u = 0; u < 4; u++) add8(v[u]);
    }
    for (; i < deg; i++) add8(__ldg(&H[(size_t)__ldg(&sl[i]) * 8 + q]));

    float4* o4 = (float4*)out;
    float4 oa = o4[(size_t)node * 16 + 2 * q];
    float4 ob = o4[(size_t)node * 16 + 2 * q + 1];
    oa.x += acc[0]; oa.y += acc[1]; oa.z += acc[2]; oa.w += acc[3];
    ob.x += acc[4]; ob.y += acc[5]; ob.z += acc[6]; ob.w += acc[7];
    o4[(size_t)node * 16 + 2 * q] = oa;
    o4[(size_t)node * 16 + 2 * q + 1] = ob;
}

// Rare overflow edges (deg > CAP): add W2[t]*x[src] + b2[t] to out[dst].
__global__ void ovf_kernel(const float* __restrict__ x,
                           const int* __restrict__ ntype,
                           const float* __restrict__ W2,
                           const float* __restrict__ b2,
                           float* __restrict__ out) {
    int n = g_ovf_cnt;
    if (n > 8192) n = 8192;
    int wid = (blockIdx.x * blockDim.x + threadIdx.x) >> 5;
    int lane = threadIdx.x & 31;
    int nwarps = (gridDim.x * blockDim.x) >> 5;
    for (int ei = wid; ei < n; ei += nwarps) {
        int2 sd = g_ovf[ei];
        int src = sd.x, dst = sd.y;
        int t = ntype[src];
        int c = lane * 2;
        float s0 = b2[t * 64 + c], s1 = b2[t * 64 + c + 1];
        for (int k = 0; k < 64; k++) {
            float xv = __ldg(&x[src * 64 + k]);
            s0 += xv * __ldg(&W2[t * 4096 + k * 64 + c]);
            s1 += xv * __ldg(&W2[t * 4096 + k * 64 + c + 1]);
        }
        atomicAdd(&out[(size_t)dst * 64 + c], s0);
        atomicAdd(&out[(size_t)dst * 64 + c + 1], s1);
    }
}

// ---------------- launch ----------------
extern "C" void kernel_launch(void* const* d_in, const int* in_sizes, int n_in,
                              void* d_out, int out_size) {
    const float *x = nullptr, *ef = nullptr;
    const float *W[4] = {nullptr, nullptr, nullptr, nullptr};
    const float *B[4] = {nullptr, nullptr, nullptr, nullptr};
    const float *W5 = nullptr, *b5 = nullptr;
    const int *ntype = nullptr, *esrc = nullptr, *edst = nullptr, *etype = nullptr;
    int wI = 0, bI = 0, mI = 0;
    for (int i = 0; i < n_in; i++) {
        long s = in_sizes[i];
        const void* p = d_in[i];
        if (s == (long)Nn * 64)       x = (const float*)p;
        else if (s == (long)Mm * 16)  ef = (const float*)p;
        else if (s == Nn)             ntype = (const int*)p;
        else if (s == Mm) {
            if (mI == 0) esrc = (const int*)p;
            else if (mI == 1) edst = (const int*)p;
            else etype = (const int*)p;
            mI++;
        }
        else if (s == 2 * 64 * 64) { if (wI < 4) W[wI++] = (const float*)p; }
        else if (s == 2 * 64)      { if (bI < 4) B[bI++] = (const float*)p; }
        else if (s == 3 * 16 * 64) W5 = (const float*)p;
        else if (s == 3 * 64)      b5 = (const float*)p;
    }
    float* out = (float*)d_out;

    // Side stream for the edge-independent h2 GEMM (captured via event fork).
    cudaStream_t s2;
    cudaEvent_t evFork, evJoin;
    bool forked = (cudaStreamCreateWithFlags(&s2, cudaStreamNonBlocking) == cudaSuccess)
               && (cudaEventCreateWithFlags(&evFork, cudaEventDisableTiming) == cudaSuccess)
               && (cudaEventCreateWithFlags(&evJoin, cudaEventDisableTiming) == cudaSuccess);

    const int h2_smem = 4096 * 4 + 128 * 4;   // 16.5 KB
    const int h1_smem = 6144 * 4 + 128 * 4;   // 24.5 KB

    if (forked) {
        cudaEventRecord(evFork, 0);
        cudaStreamWaitEvent(s2, evFork, 0);
        h2_gemm_kernel<<<296, 256, h2_smem, s2>>>(x, ntype, W[1], B[1]);
        cudaEventRecord(evJoin, s2);
    } else {
        h2_gemm_kernel<<<296, 256, h2_smem>>>(x, ntype, W[1], B[1]);
    }

    zero_kernel<<<1024, 256>>>();
    edge_scatter_kernel<<<(Mm * 2 + 255) / 256, 256>>>(ef, esrc, edst, etype);
    h1_gemm_kernel<<<296, 256, h1_smem>>>(x, ntype, W[0], B[0], W5, b5, out);
    if (forked) cudaStreamWaitEvent(0, evJoin, 0);
    h2_gather_kernel<<<(Nn + 31) / 32, 256>>>(out);
    ovf_kernel<<<8, 256>>>(x, ntype, W[1], B[1], out);
}